// round 14
// baseline (speedup 1.0000x reference)
#include <cuda_runtime.h>

#define NSEG 128
#define KC   64
#define BZD  64

constexpr int PIX = 32;                               // consecutive y pixels per thread (half row)
constexpr int NW = 4;                                 // warps per block (K split 4 ways)
constexpr int THREADS = 32 * NW;                      // 128
constexpr int TPR = BZD / PIX;                        // 2 threads per row
constexpr int ROWS_PER_BLOCK = 32 / TPR;              // 16
constexpr int TILES_PER_SEG = BZD / ROWS_PER_BLOCK;   // 4
constexpr int NPAIR = PIX / 2;                        // 16
constexpr int KQ = KC / NW;                           // 16 components per warp

typedef unsigned long long u64;

__device__ __forceinline__ float ex2f(float x) {
    float r; asm("ex2.approx.ftz.f32 %0, %1;" : "=f"(r) : "f"(x)); return r;
}
__device__ __forceinline__ float rcpf(float x) {
    float r; asm("rcp.approx.ftz.f32 %0, %1;" : "=f"(r) : "f"(x)); return r;
}
__device__ __forceinline__ u64 pk2(float lo, float hi) {
    u64 r; asm("mov.b64 %0, {%1,%2};" : "=l"(r) : "f"(lo), "f"(hi)); return r;
}
__device__ __forceinline__ void upk2(float& lo, float& hi, u64 v) {
    asm("mov.b64 {%0,%1}, %2;" : "=f"(lo), "=f"(hi) : "l"(v));
}
__device__ __forceinline__ u64 fma2(u64 a, u64 b, u64 c) {
    u64 r; asm("fma.rn.f32x2 %0, %1, %2, %3;" : "=l"(r) : "l"(a), "l"(b), "l"(c)); return r;
}
__device__ __forceinline__ u64 add2(u64 a, u64 b) {
    u64 r; asm("add.rn.f32x2 %0, %1, %2;" : "=l"(r) : "l"(a), "l"(b)); return r;
}
__device__ __forceinline__ u64 mul2(u64 a, u64 b) {
    u64 r; asm("mul.rn.f32x2 %0, %1, %2;" : "=l"(r) : "l"(a), "l"(b)); return r;
}

__global__ __launch_bounds__(THREADS)
void seg_splat_kernel(const float* __restrict__ u,
                      const float* __restrict__ a,
                      const float* __restrict__ B,
                      float* __restrict__ out)
{
    __shared__ float4 sK1[KC];              // {A', Bc', -ux, -uy}
    __shared__ float4 sK2[KC];              // {C', 2C'h, Bc'h, gamma}
    __shared__ float4 sK3[KC];              // {s4, a, s8, pad}
    __shared__ ulonglong2 sP[NW][NPAIR][32];// per-warp partials {num, den}  (32KB)

    const int n    = blockIdx.x / TILES_PER_SEG;
    const int tile = blockIdx.x % TILES_PER_SEG;
    const int tid  = threadIdx.x;
    const int lane = tid & 31;
    const int wid  = tid >> 5;              // which K quarter

    const float h = 1.0f / BZD;

    // Per-component constants: one k per thread for tid < KC
    if (tid < KC) {
        const int k = tid;
        const float* bp = B + (size_t)(n * KC + k) * 4;
        float b00 = bp[0], b10 = bp[2], b11 = bp[3];
        const float L = -0.72134752044448170368f;   // -0.5 * log2(e)
        float A  = L * (b00 * b00 + b10 * b10);
        float Bc = 2.0f * L * (b10 * b11);
        float C  = L * (b11 * b11);
        float gamma = C * (h * h);                  // per-pixel-step quadratic (log2)
        float s2 = ex2f(2.0f * gamma);
        float s4 = s2 * s2;
        float s8 = s4 * s4;
        const float* up = u + (size_t)(n * KC + k) * 2;
        float av = a[n * KC + k];
        sK1[k] = make_float4(A, Bc, -up[0], -up[1]);
        sK2[k] = make_float4(C, 2.0f * C * h, Bc * h, gamma);
        sK3[k] = make_float4(s4, av, s8, 0.0f);
    }
    __syncthreads();

    const int row = lane >> 1;                      // 16 rows per warp-tile
    const int j0  = (lane & 1) * PIX;               // half-row strip start
    const int i   = tile * ROWS_PER_BLOCK + row;

    const float xi = ((float)i  + 0.5f) * h;
    const float y0 = ((float)j0 + 0.5f) * h;

    u64 num2[NPAIR], den2[NPAIR];
    const u64 zz = pk2(0.0f, 0.0f);
#pragma unroll
    for (int p = 0; p < NPAIR; p++) { num2[p] = zz; den2[p] = zz; }

    const float4* p1 = sK1 + wid * KQ;
    const float4* p2 = sK2 + wid * KQ;
    const float4* p3 = sK3 + wid * KQ;

#pragma unroll 1
    for (int kk = 0; kk < KQ; kk++) {
        float4 k1 = p1[kk];
        float4 k2 = p2[kk];
        float4 k3 = p3[kk];

        // e(t) = E0 + t*beta + t^2*gamma (log2 domain), t = pixel index in 32-px strip
        float dx   = xi + k1.z;
        float dy   = y0 + k1.w;
        float t1   = fmaf(k1.x, dx, k1.y * dy);             // A*dx + Bc*dy
        float E0   = fmaf(dx, t1, dy * (k2.x * dy));        // A dx^2 + Bc dx dy + C dy^2
        float bpg  = fmaf(k2.y, dy, fmaf(k2.z, dx, k2.w));  // beta + gamma = e(1)-e(0)
        float E1   = E0 + bpg;                              // e(1)
        float tg   = bpg + k2.w;                            // beta + 2*gamma

        // three independent MUFU seeds
        float kv0 = ex2f(E0);
        float kv1 = ex2f(E1);
        float rlo = ex2f(tg + tg);                          // 2^(2*beta+4*gamma)
        float rhi = rlo * k3.x;                             // 2^(2*beta+8*gamma)

        u64 kvA = pk2(kv0, kv1);
        u64 rA  = pk2(rlo, rhi);
        u64 a2  = pk2(k3.y, k3.y);
        u64 s82 = pk2(k3.z, k3.z);

#pragma unroll
        for (int p = 0; p < NPAIR; p++) {
            den2[p] = add2(den2[p], kvA);
            num2[p] = fma2(a2, kvA, num2[p]);
            if (p < NPAIR - 1) kvA = mul2(kvA, rA);         // advance 2 pixels
            if (p < NPAIR - 2) rA  = mul2(rA, s82);         // quadratic ratio update
        }
    }

    // All warps publish fused {num,den} partials (STS.128)
#pragma unroll
    for (int p = 0; p < NPAIR; p++) {
        ulonglong2 v; v.x = num2[p]; v.y = den2[p];
        sP[wid][p][lane] = v;
    }
    __syncthreads();

    // Warp w reduces pixel-pairs [4w, 4w+4): pixels [8w, 8w+8) of each strip
    float res[8];
#pragma unroll
    for (int q = 0; q < 4; q++) {
        const int p = 4 * wid + q;
        ulonglong2 v0 = sP[0][p][lane];
        ulonglong2 v1 = sP[1][p][lane];
        ulonglong2 v2 = sP[2][p][lane];
        ulonglong2 v3 = sP[3][p][lane];
        u64 nt = add2(add2(v0.x, v1.x), add2(v2.x, v3.x));
        u64 dt = add2(add2(v0.y, v1.y), add2(v2.y, v3.y));
        float n0, n1, d0, d1;
        upk2(n0, n1, nt);
        upk2(d0, d1, dt);
        res[2 * q]     = n0 * rcpf(fmaxf(d0, 1e-7f));
        res[2 * q + 1] = n1 * rcpf(fmaxf(d1, 1e-7f));
    }
    float4* op = (float4*)(out + (size_t)n * (BZD * BZD) + (size_t)i * BZD + j0 + 8 * wid);
    op[0] = ((float4*)res)[0];
    op[1] = ((float4*)res)[1];
}

extern "C" void kernel_launch(void* const* d_in, const int* in_sizes, int n_in,
                              void* d_out, int out_size)
{
    const float* u = (const float*)d_in[0];
    const float* a = (const float*)d_in[1];
    const float* B = (const float*)d_in[2];
    float* out     = (float*)d_out;

    int blocks = NSEG * TILES_PER_SEG;   // 512 blocks x 4 warps
    seg_splat_kernel<<<blocks, THREADS>>>(u, a, B, out);
}

// round 15
// speedup vs baseline: 1.0230x; 1.0230x over previous
#include <cuda_runtime.h>

#define NSEG 128
#define KC   64
#define BZD  64

constexpr int PIX = 16;                               // consecutive y pixels per thread
constexpr int NW = 4;                                 // warps per block (K split 4 ways)
constexpr int THREADS = 32 * NW;                      // 128
constexpr int TPR = BZD / PIX;                        // 4 threads per row
constexpr int ROWS_PER_BLOCK = 32 / TPR;              // 8
constexpr int TILES_PER_SEG = BZD / ROWS_PER_BLOCK;   // 8
constexpr int NPAIR = PIX / 2;                        // 8
constexpr int KQ = KC / NW;                           // 16 components per warp

typedef unsigned long long u64;

__device__ __forceinline__ float ex2f(float x) {
    float r; asm("ex2.approx.ftz.f32 %0, %1;" : "=f"(r) : "f"(x)); return r;
}
__device__ __forceinline__ float rcpf(float x) {
    float r; asm("rcp.approx.ftz.f32 %0, %1;" : "=f"(r) : "f"(x)); return r;
}
__device__ __forceinline__ u64 pk2(float lo, float hi) {
    u64 r; asm("mov.b64 %0, {%1,%2};" : "=l"(r) : "f"(lo), "f"(hi)); return r;
}
__device__ __forceinline__ void upk2(float& lo, float& hi, u64 v) {
    asm("mov.b64 {%0,%1}, %2;" : "=f"(lo), "=f"(hi) : "l"(v));
}
__device__ __forceinline__ u64 fma2(u64 a, u64 b, u64 c) {
    u64 r; asm("fma.rn.f32x2 %0, %1, %2, %3;" : "=l"(r) : "l"(a), "l"(b), "l"(c)); return r;
}
__device__ __forceinline__ u64 add2(u64 a, u64 b) {
    u64 r; asm("add.rn.f32x2 %0, %1, %2;" : "=l"(r) : "l"(a), "l"(b)); return r;
}
__device__ __forceinline__ u64 mul2(u64 a, u64 b) {
    u64 r; asm("mul.rn.f32x2 %0, %1, %2;" : "=l"(r) : "l"(a), "l"(b)); return r;
}

__global__ __launch_bounds__(THREADS)
void seg_splat_kernel(const float* __restrict__ u,
                      const float* __restrict__ a,
                      const float* __restrict__ B,
                      float* __restrict__ out)
{
    __shared__ float4 sK1[KC];              // {A', Bc', ux, uy}
    __shared__ float4 sK2[KC];              // {C', 2C'h, gamma, s2}
    __shared__ float2 sK3[KC];              // {s4, a}
    __shared__ u64    sS8[KC];              // {s8, s8}
    __shared__ u64 sNum[NW][NPAIR][32];     // per-warp partials
    __shared__ u64 sDen[NW][NPAIR][32];

    const int n    = blockIdx.x / TILES_PER_SEG;
    const int tile = blockIdx.x % TILES_PER_SEG;
    const int tid  = threadIdx.x;
    const int lane = tid & 31;
    const int wid  = tid >> 5;              // which K quarter

    const float h = 1.0f / BZD;

    // Per-component constants: one k per thread for tid < KC
    if (tid < KC) {
        const int k = tid;
        const float* bp = B + (size_t)(n * KC + k) * 4;
        float b00 = bp[0], b10 = bp[2], b11 = bp[3];
        const float L = -0.72134752044448170368f;   // -0.5 * log2(e)
        float A  = L * (b00 * b00 + b10 * b10);
        float Bc = 2.0f * L * (b10 * b11);
        float C  = L * (b11 * b11);
        float gamma = C * (h * h);
        float s2 = ex2f(2.0f * gamma);
        float s4 = s2 * s2;
        float s8 = s4 * s4;
        const float* up = u + (size_t)(n * KC + k) * 2;
        float av = a[n * KC + k];
        sK1[k] = make_float4(A, Bc, up[0], up[1]);
        sK2[k] = make_float4(C, 2.0f * C * h, gamma, s2);
        sK3[k] = make_float2(s4, av);
        sS8[k] = pk2(s8, s8);
    }
    __syncthreads();

    const int row = lane / TPR;
    const int j0  = (lane % TPR) * PIX;
    const int i   = tile * ROWS_PER_BLOCK + row;

    const float xi = ((float)i  + 0.5f) * h;
    const float y0 = ((float)j0 + 0.5f) * h;

    u64 num2[NPAIR], den2[NPAIR];
    const u64 zz = pk2(0.0f, 0.0f);
#pragma unroll
    for (int p = 0; p < NPAIR; p++) { num2[p] = zz; den2[p] = zz; }

    const int kbeg = wid * KQ;
#pragma unroll 2
    for (int kk = 0; kk < KQ; kk++) {
        const int k = kbeg + kk;
        float4 k1 = sK1[k];
        float4 k2 = sK2[k];
        float2 k3 = sK3[k];
        u64  s8_2 = sS8[k];

        float dx  = xi - k1.z;
        float dy0 = y0 - k1.w;
        float bdx = k1.y * dx;                       // Bc'*dx
        float adx = k1.x * dx;                       // A'*dx
        float t3  = fmaf(k2.x, dy0, bdx);            // C'*dy0 + Bc'*dx
        float E0  = fmaf(dy0, t3, adx * dx);         // exponent at t=0 (log2 domain)
        float beta = fmaf(k2.y, dy0, bdx * h);       // h*(Bc'dx + 2C'dy0)
        float bpg = beta + k2.z;                     // beta + gamma

        float kv0 = ex2f(E0);
        float w   = ex2f(bpg);
        float kv1 = kv0 * w;
        float w2  = w * w;
        float rlo = w2 * k2.w;                       // stride-2 ratio, even lane
        float rhi = rlo * k3.x;                      // stride-2 ratio, odd lane

        u64 kv2 = pk2(kv0, kv1);
        u64 r2  = pk2(rlo, rhi);
        u64 a2  = pk2(k3.y, k3.y);

#pragma unroll
        for (int p = 0; p < NPAIR; p++) {
            den2[p] = add2(den2[p], kv2);
            num2[p] = fma2(a2, kv2, num2[p]);
            if (p < NPAIR - 1) kv2 = mul2(kv2, r2);   // advance 2 pixels
            if (p < NPAIR - 2) r2  = mul2(r2, s8_2);  // quadratic ratio update (last is dead)
        }
    }

    // Cross-warp K reduction
#pragma unroll
    for (int p = 0; p < NPAIR; p++) {
        sNum[wid][p][lane] = num2[p];
        sDen[wid][p][lane] = den2[p];
    }
    __syncthreads();

    // Warp w reduces pixel-pairs {2w, 2w+1}: pixels [4w, 4w+4) of each strip
    float res[4];
#pragma unroll
    for (int q = 0; q < 2; q++) {
        const int p = 2 * wid + q;
        u64 nt = add2(add2(sNum[0][p][lane], sNum[1][p][lane]),
                      add2(sNum[2][p][lane], sNum[3][p][lane]));
        u64 dt = add2(add2(sDen[0][p][lane], sDen[1][p][lane]),
                      add2(sDen[2][p][lane], sDen[3][p][lane]));
        float n0, n1, d0, d1;
        upk2(n0, n1, nt);
        upk2(d0, d1, dt);
        res[2 * q]     = n0 * rcpf(fmaxf(d0, 1e-7f));
        res[2 * q + 1] = n1 * rcpf(fmaxf(d1, 1e-7f));
    }
    float4* op = (float4*)(out + (size_t)n * (BZD * BZD) + (size_t)i * BZD + j0 + 4 * wid);
    op[0] = ((float4*)res)[0];
}

extern "C" void kernel_launch(void* const* d_in, const int* in_sizes, int n_in,
                              void* d_out, int out_size)
{
    const float* u = (const float*)d_in[0];
    const float* a = (const float*)d_in[1];
    const float* B = (const float*)d_in[2];
    float* out     = (float*)d_out;

    int blocks = NSEG * TILES_PER_SEG;   // 1024 blocks x 4 warps
    seg_splat_kernel<<<blocks, THREADS>>>(u, a, B, out);
}

// round 16
// speedup vs baseline: 1.1976x; 1.1707x over previous
#include <cuda_runtime.h>

#define NSEG 128
#define KC   64
#define BZD  64

constexpr int PIX = 16;                               // consecutive y pixels per thread
constexpr int NW = 4;                                 // warps per block (K split 4 ways)
constexpr int THREADS = 32 * NW;                      // 128
constexpr int TPR = BZD / PIX;                        // 4 threads per row
constexpr int ROWS_PER_BLOCK = 32 / TPR;              // 8
constexpr int TILES_PER_SEG = BZD / ROWS_PER_BLOCK;   // 8
constexpr int NPAIR = PIX / 2;                        // 8
constexpr int KQ = KC / NW;                           // 16 components per warp

typedef unsigned long long u64;

__device__ __forceinline__ float ex2f(float x) {
    float r; asm("ex2.approx.ftz.f32 %0, %1;" : "=f"(r) : "f"(x)); return r;
}
__device__ __forceinline__ float rcpf(float x) {
    float r; asm("rcp.approx.ftz.f32 %0, %1;" : "=f"(r) : "f"(x)); return r;
}
__device__ __forceinline__ u64 pk2(float lo, float hi) {
    u64 r; asm("mov.b64 %0, {%1,%2};" : "=l"(r) : "f"(lo), "f"(hi)); return r;
}
__device__ __forceinline__ void upk2(float& lo, float& hi, u64 v) {
    asm("mov.b64 {%0,%1}, %2;" : "=f"(lo), "=f"(hi) : "l"(v));
}
__device__ __forceinline__ u64 fma2(u64 a, u64 b, u64 c) {
    u64 r; asm("fma.rn.f32x2 %0, %1, %2, %3;" : "=l"(r) : "l"(a), "l"(b), "l"(c)); return r;
}
__device__ __forceinline__ u64 add2(u64 a, u64 b) {
    u64 r; asm("add.rn.f32x2 %0, %1, %2;" : "=l"(r) : "l"(a), "l"(b)); return r;
}
__device__ __forceinline__ u64 mul2(u64 a, u64 b) {
    u64 r; asm("mul.rn.f32x2 %0, %1, %2;" : "=l"(r) : "l"(a), "l"(b)); return r;
}

__global__ __launch_bounds__(THREADS)
void seg_splat_kernel(const float* __restrict__ u,
                      const float* __restrict__ a,
                      const float* __restrict__ B,
                      float* __restrict__ out)
{
    __shared__ float4 sK1[KC];              // {A', Bc', ux, uy}
    __shared__ float4 sK2[KC];              // {C', 2C'h, gamma, s2}
    __shared__ float2 sK3[KC];              // {s4, a}
    __shared__ u64    sS8[KC];              // {s8, s8}
    __shared__ u64 sNum[NW][NPAIR][32];     // per-warp partials
    __shared__ u64 sDen[NW][NPAIR][32];

    const int n    = blockIdx.x / TILES_PER_SEG;
    const int tile = blockIdx.x % TILES_PER_SEG;
    const int tid  = threadIdx.x;
    const int lane = tid & 31;
    const int wid  = tid >> 5;              // which K quarter

    const float h = 1.0f / BZD;

    // Per-component constants: one k per thread for tid < KC
    if (tid < KC) {
        const int k = tid;
        const float* bp = B + (size_t)(n * KC + k) * 4;
        float b00 = bp[0], b10 = bp[2], b11 = bp[3];
        const float L = -0.72134752044448170368f;   // -0.5 * log2(e)
        float A  = L * (b00 * b00 + b10 * b10);
        float Bc = 2.0f * L * (b10 * b11);
        float C  = L * (b11 * b11);
        float gamma = C * (h * h);
        float s2 = ex2f(2.0f * gamma);
        float s4 = s2 * s2;
        float s8 = s4 * s4;
        const float* up = u + (size_t)(n * KC + k) * 2;
        float av = a[n * KC + k];
        sK1[k] = make_float4(A, Bc, up[0], up[1]);
        sK2[k] = make_float4(C, 2.0f * C * h, gamma, s2);
        sK3[k] = make_float2(s4, av);
        sS8[k] = pk2(s8, s8);
    }
    __syncthreads();

    const int row = lane / TPR;
    const int j0  = (lane % TPR) * PIX;
    const int i   = tile * ROWS_PER_BLOCK + row;

    const float xi = ((float)i  + 0.5f) * h;
    const float y0 = ((float)j0 + 0.5f) * h;

    u64 num2[NPAIR], den2[NPAIR];
    const u64 zz = pk2(0.0f, 0.0f);
#pragma unroll
    for (int p = 0; p < NPAIR; p++) { num2[p] = zz; den2[p] = zz; }

    const int kbeg = wid * KQ;
#pragma unroll 2
    for (int kk = 0; kk < KQ; kk++) {
        const int k = kbeg + kk;
        float4 k1 = sK1[k];
        float4 k2 = sK2[k];
        float2 k3 = sK3[k];
        u64  s8_2 = sS8[k];

        float dx  = xi - k1.z;
        float dy0 = y0 - k1.w;
        float bdx = k1.y * dx;                       // Bc'*dx
        float adx = k1.x * dx;                       // A'*dx
        float t3  = fmaf(k2.x, dy0, bdx);            // C'*dy0 + Bc'*dx
        float E0  = fmaf(dy0, t3, adx * dx);         // exponent at t=0 (log2 domain)
        float beta = fmaf(k2.y, dy0, bdx * h);       // h*(Bc'dx + 2C'dy0)
        float bpg = beta + k2.z;                     // beta + gamma

        float kv0 = ex2f(E0);
        float w   = ex2f(bpg);
        float kv1 = kv0 * w;
        float w2  = w * w;
        float rlo = w2 * k2.w;                       // stride-2 ratio, even lane
        float rhi = rlo * k3.x;                      // stride-2 ratio, odd lane

        u64 kv2 = pk2(kv0, kv1);
        u64 r2  = pk2(rlo, rhi);
        u64 a2  = pk2(k3.y, k3.y);

#pragma unroll
        for (int p = 0; p < NPAIR; p++) {
            den2[p] = add2(den2[p], kv2);
            num2[p] = fma2(a2, kv2, num2[p]);
            if (p < NPAIR - 1) {
                kv2 = mul2(kv2, r2);                 // advance 2 pixels
                r2  = mul2(r2, s8_2);                // quadratic ratio update
            }
        }
    }

    // All warps publish partials
#pragma unroll
    for (int p = 0; p < NPAIR; p++) {
        sNum[wid][p][lane] = num2[p];
        sDen[wid][p][lane] = den2[p];
    }
    __syncthreads();

    // Warp w reduces pixel-pairs {2w, 2w+1}: pixels [4w, 4w+4) of each strip
    float res[4];
#pragma unroll
    for (int q = 0; q < 2; q++) {
        const int p = 2 * wid + q;
        u64 nt = add2(add2(sNum[0][p][lane], sNum[1][p][lane]),
                      add2(sNum[2][p][lane], sNum[3][p][lane]));
        u64 dt = add2(add2(sDen[0][p][lane], sDen[1][p][lane]),
                      add2(sDen[2][p][lane], sDen[3][p][lane]));
        float n0, n1, d0, d1;
        upk2(n0, n1, nt);
        upk2(d0, d1, dt);
        res[2 * q]     = n0 * rcpf(fmaxf(d0, 1e-7f));
        res[2 * q + 1] = n1 * rcpf(fmaxf(d1, 1e-7f));
    }
    float4* op = (float4*)(out + (size_t)n * (BZD * BZD) + (size_t)i * BZD + j0 + 4 * wid);
    op[0] = ((float4*)res)[0];
}

extern "C" void kernel_launch(void* const* d_in, const int* in_sizes, int n_in,
                              void* d_out, int out_size)
{
    const float* u = (const float*)d_in[0];
    const float* a = (const float*)d_in[1];
    const float* B = (const float*)d_in[2];
    float* out     = (float*)d_out;

    int blocks = NSEG * TILES_PER_SEG;   // 1024 blocks x 4 warps
    seg_splat_kernel<<<blocks, THREADS>>>(u, a, B, out);
}